// round 14
// baseline (speedup 1.0000x reference)
#include <cuda_runtime.h>
#include <cuda_bf16.h>

// GANLoss: out = -mean(prob[n, targets[n]] * reward[n]), N=8192, C=32000.
// SINGLE node. ONE-STAGE producers: each of 256 producer warps gathers 32
// rows, 5-shuffle reduces, and fire-and-forgets one st.release.gpu.u64
// {flag|payload} into its own slot. No smem, no syncthreads, no 2nd stage.
// Consumer (block 0, 1 warp, spinning from launch): lane i consumes its 8
// slots in FIXED index order (deterministic -> rel_err 0), accumulating as
// they arrive; then 5 shuffles + store + slot reset for graph replay.
// 33 CTAs co-resident on 148 SMs -> spin cannot deadlock.

#define NPRODUCERS   32
#define NTHREADS     256
#define NSLOTS       (NPRODUCERS * NTHREADS / 32)   // 256
#define SLOTS_PER_LANE (NSLOTS / 32)                // 8

__device__ unsigned long long g_slots[NSLOTS];   // zero-initialized

__global__ __launch_bounds__(NTHREADS) void ganloss_kernel(
    const float* __restrict__ prob,
    const int* __restrict__ targets,
    const float* __restrict__ reward,
    float* __restrict__ out,
    int N, unsigned int C, float neg_inv_n)
{
    const int lane = threadIdx.x & 31;

    if (blockIdx.x == 0) {
        // ---- dedicated consumer: spinning from launch ----
        if (threadIdx.x < 32) {
            float acc = 0.0f;
            #pragma unroll
            for (int j = 0; j < SLOTS_PER_LANE; j++) {
                const int s = lane * SLOTS_PER_LANE + j;   // fixed order
                unsigned long long word;
                do {
                    asm volatile("ld.acquire.gpu.u64 %0, [%1];"
                                 : "=l"(word) : "l"(&g_slots[s]) : "memory");
                } while (!(word >> 63));
                acc += __uint_as_float((unsigned int)word);
            }

            #pragma unroll
            for (int off = 16; off > 0; off >>= 1)
                acc += __shfl_xor_sync(0xFFFFFFFFu, acc, off);

            if (lane == 0)
                out[0] = acc * neg_inv_n;

            // reset slots for the next graph replay
            #pragma unroll
            for (int j = 0; j < SLOTS_PER_LANE; j++)
                g_slots[lane * SLOTS_PER_LANE + j] = 0ULL;
        }
        return;
    }

    // ---- producers: blocks 1..32, one slot per warp ----
    const int idx = (blockIdx.x - 1) * NTHREADS + threadIdx.x;

    float v = 0.0f;
    if (idx < N) {
        unsigned int t = (unsigned int)targets[idx];
        unsigned int off32 = (unsigned int)idx * C + t;   // N*C < 2^31
        v = __ldg(&prob[off32]) * __ldg(&reward[idx]);
    }

    // warp reduce (5 shuffles) — the only reduction stage
    #pragma unroll
    for (int off = 16; off > 0; off >>= 1)
        v += __shfl_xor_sync(0xFFFFFFFFu, v, off);

    if (lane == 0) {
        const int slot = (blockIdx.x - 1) * (NTHREADS / 32) + (threadIdx.x >> 5);
        unsigned long long word =
            (1ULL << 63) | (unsigned long long)__float_as_uint(v);
        asm volatile("st.release.gpu.u64 [%0], %1;"
                     :: "l"(&g_slots[slot]), "l"(word) : "memory");
    }
}

extern "C" void kernel_launch(void* const* d_in, const int* in_sizes, int n_in,
                              void* d_out, int out_size)
{
    const float* prob    = (const float*)d_in[0];
    const int*   targets = (const int*)d_in[1];
    const float* reward  = (const float*)d_in[2];
    float*       out     = (float*)d_out;

    const int N = in_sizes[2];                              // 8192
    const unsigned int C = (unsigned int)(in_sizes[0] / N); // 32000

    ganloss_kernel<<<NPRODUCERS + 1, NTHREADS>>>(prob, targets, reward, out,
                                                 N, C, -1.0f / (float)N);
}

// round 15
// speedup vs baseline: 1.3014x; 1.3014x over previous
#include <cuda_runtime.h>
#include <cuda_bf16.h>

// GANLoss: out = -mean(prob[n, targets[n]] * reward[n]), N=8192, C=32000.
// Best measured design (R10, 6.59us) + 32-bit indexing:
// Two kernels with full-overlap PDL: gather triggers launch-completion at
// ENTRY so the finalize warp is resident+spinning during the gather. Each
// gather CTA block-reduces and fire-and-forgets ONE st.release.gpu.u64
// {flag|payload} into its slot; finalize lane i acquire-spins on slot i
// (32 parallel addresses), fixed-order reduces (rel_err 0), writes out,
// resets slots for graph replay.

#define NBLOCKS  32
#define NTHREADS 256

__device__ unsigned long long g_slots[NBLOCKS];   // zero-initialized

__global__ __launch_bounds__(NTHREADS) void gather_kernel(
    const float* __restrict__ prob,
    const int* __restrict__ targets,
    const float* __restrict__ reward,
    int N, unsigned int C)
{
    // Release the dependent finalize grid immediately; data visibility is
    // handled by the release/acquire slot protocol below.
    cudaTriggerProgrammaticLaunchCompletion();

    const int idx  = blockIdx.x * blockDim.x + threadIdx.x;
    const int lane = threadIdx.x & 31;
    const int wid  = threadIdx.x >> 5;

    float v = 0.0f;
    if (idx < N) {
        unsigned int t = (unsigned int)targets[idx];
        unsigned int off32 = (unsigned int)idx * C + t;   // N*C < 2^31
        v = __ldg(&prob[off32]) * __ldg(&reward[idx]);
    }

    // warp reduce (5 shuffles)
    #pragma unroll
    for (int off = 16; off > 0; off >>= 1)
        v += __shfl_xor_sync(0xFFFFFFFFu, v, off);

    __shared__ float s_warp[NTHREADS / 32];
    if (lane == 0) s_warp[wid] = v;
    __syncthreads();

    if (threadIdx.x < 32) {
        float w = (lane < NTHREADS / 32) ? s_warp[lane] : 0.0f;
        #pragma unroll
        for (int off = 4; off > 0; off >>= 1)
            w += __shfl_xor_sync(0xFFFFFFFFu, w, off);
        if (lane == 0) {
            unsigned long long word =
                (1ULL << 63) | (unsigned long long)__float_as_uint(w);
            // single fire-and-forget release store: flag + payload together
            asm volatile("st.release.gpu.u64 [%0], %1;"
                         :: "l"(&g_slots[blockIdx.x]), "l"(word) : "memory");
        }
    }
}

__global__ __launch_bounds__(32) void finalize_kernel(
    float* __restrict__ out, float neg_inv_n)
{
    const int lane = threadIdx.x;

    // Released early by the gather's entry trigger; each lane spins on its
    // own slot (32 independent addresses, fully parallel).
    unsigned long long word;
    do {
        asm volatile("ld.acquire.gpu.u64 %0, [%1];"
                     : "=l"(word) : "l"(&g_slots[lane]) : "memory");
    } while (!(word >> 63));

    float v = __uint_as_float((unsigned int)word);

    #pragma unroll
    for (int off = 16; off > 0; off >>= 1)
        v += __shfl_xor_sync(0xFFFFFFFFu, v, off);

    if (lane == 0)
        out[0] = v * neg_inv_n;

    // reset slots for the next graph replay (stream-order visible)
    g_slots[lane] = 0ULL;
}

extern "C" void kernel_launch(void* const* d_in, const int* in_sizes, int n_in,
                              void* d_out, int out_size)
{
    const float* prob    = (const float*)d_in[0];
    const int*   targets = (const int*)d_in[1];
    const float* reward  = (const float*)d_in[2];
    float*       out     = (float*)d_out;

    const int N = in_sizes[2];                              // 8192
    const unsigned int C = (unsigned int)(in_sizes[0] / N); // 32000

    gather_kernel<<<NBLOCKS, NTHREADS>>>(prob, targets, reward, N, C);

    cudaLaunchConfig_t cfg = {};
    cfg.gridDim  = dim3(1, 1, 1);
    cfg.blockDim = dim3(32, 1, 1);
    cfg.dynamicSmemBytes = 0;
    cfg.stream = 0;
    cudaLaunchAttribute attr;
    attr.id = cudaLaunchAttributeProgrammaticStreamSerialization;
    attr.val.programmaticStreamSerializationAllowed = 1;
    cfg.attrs = &attr;
    cfg.numAttrs = 1;

    float neg_inv_n = -1.0f / (float)N;
    cudaLaunchKernelEx(&cfg, finalize_kernel, out, neg_inv_n);
}